// round 3
// baseline (speedup 1.0000x reference)
#include <cuda_runtime.h>
#include <math.h>

#define MAXN 2048
#define MAXD 64

__device__ float g_x2[MAXN];          // ||x_i||^2
__device__ float g_l[MAXN];           // x_tan_i . w_l
__device__ float g_r[MAXN];           // x_tan_i . w_r
__device__ int   g_cnt[MAXN];         // neighbors per row
__device__ int   g_j[MAXN * MAXD];    // neighbor indices (dense, deterministic order)
__device__ float g_g[MAXN * MAXD];    // per-pair weight g
__device__ float g_h[MAXN * MAXD];    // per-pair g*alpha

__device__ __forceinline__ float warp_sum(float v) {
#pragma unroll
    for (int o = 16; o; o >>= 1) v += __shfl_xor_sync(0xffffffffu, v, o);
    return v;
}

// K1: one warp per row. Precompute row scalars AND compact the adj row into a
// dense neighbor list with a fixed deterministic ordering (no atomics).
__global__ void scan_kernel(const float* __restrict__ x,
                            const float* __restrict__ adj,
                            const float* __restrict__ att_w, int N) {
    int row  = blockIdx.x * (blockDim.x >> 5) + (threadIdx.x >> 5);
    int lane = threadIdx.x & 31;
    if (row >= N) return;

    // per-row precompute (logmap0 projections + norm)
    float x0 = x[row * 64 + lane];
    float x1 = x[row * 64 + 32 + lane];
    float wl0 = att_w[lane],      wl1 = att_w[32 + lane];
    float wr0 = att_w[64 + lane], wr1 = att_w[96 + lane];
    float n2 = warp_sum(x0 * x0 + x1 * x1);
    float dl = warp_sum(x0 * wl0 + x1 * wl1);
    float dr = warp_sum(x0 * wr0 + x1 * wr1);
    if (lane == 0) {
        float pn  = sqrtf(n2);
        float pnc = fmaxf(pn, 1e-15f);
        float s   = atanhf(fminf(pnc, 1.f - 1e-7f)) / pnc;
        g_x2[row] = n2;
        g_l[row]  = s * dl;
        g_r[row]  = s * dr;
    }

    // compact adj row: prefetch 12 float4/lane (512 floats per chunk-column,
    // full 1536-col row in one tile -> 12 loads in flight), then ballot/popc
    // compaction in fixed (chunk, elem, lane) order -> deterministic output.
    const float4* arow = (const float4*)(adj + (size_t)row * N);
    int nq = N >> 2;
    int base = 0;
    for (int q0 = 0; q0 < nq; q0 += 384) {
        float4 v[12];
#pragma unroll
        for (int c = 0; c < 12; c++) {
            int qi = q0 + c * 32 + lane;
            v[c] = (qi < nq) ? __ldg(&arow[qi]) : make_float4(0.f, 0.f, 0.f, 0.f);
        }
#pragma unroll
        for (int c = 0; c < 12; c++) {
            float vals[4] = {v[c].x, v[c].y, v[c].z, v[c].w};
#pragma unroll
            for (int e = 0; e < 4; e++) {
                unsigned m = __ballot_sync(0xffffffffu, vals[e] != 0.f);
                if (vals[e] != 0.f) {
                    int slot = base + __popc(m & ((1u << lane) - 1u));
                    if (slot < MAXD)
                        g_j[row * MAXD + slot] = (q0 + c * 32 + lane) * 4 + e;
                }
                base += __popc(m);
            }
        }
    }
    if (lane == 0) g_cnt[row] = min(base, MAXD);
}

// K2: one warp per pair-slot (grid-strided). Computes the pairwise dot product
// and all hyperbolic scalar math for one (i,j) pair.
__global__ void pair_kernel(const float* __restrict__ x,
                            const float* __restrict__ att_b, int N) {
    int lane = threadIdx.x & 31;
    int gw = (blockIdx.x * blockDim.x + threadIdx.x) >> 5;
    int nw = (gridDim.x * blockDim.x) >> 5;
    float bias = att_b[0];
    int total = N * MAXD;
    for (int p = gw; p < total; p += nw) {
        int i = p >> 6;            // MAXD = 64
        int s = p & 63;
        if (s >= g_cnt[i]) continue;   // uniform per warp
        int j = g_j[p];
        float xi0 = x[i * 64 + lane],      xi1 = x[i * 64 + 32 + lane];
        float xj0 = x[j * 64 + lane],      xj1 = x[j * 64 + 32 + lane];
        float D   = warp_sum(xi0 * xj0 + xi1 * xj1);
        float x2 = g_x2[i], y2 = g_x2[j];
        float li = g_l[i],  rv = g_r[j];
        float beta  = 1.f - x2;
        float alpha = 1.f - 2.f * D + y2;
        float den   = fmaxf(1.f - 2.f * D + x2 * y2, 1e-15f);
        float n2    = alpha * alpha * x2 - 2.f * alpha * beta * D
                    + beta * beta * y2;
        float sn    = fmaxf(sqrtf(fmaxf(n2, 0.f)) / den, 1e-15f);
        float ratio = atanhf(fminf(sn, 1.f - 1e-7f)) / sn;
        float w     = 1.f / (1.f + expf(-(li + rv + bias)));   // adj value is 1.0
        float g     = w * beta * ratio / den;
        if (lane == 0) {
            g_g[p] = g;
            g_h[p] = g * alpha;
        }
    }
}

// K3: one warp per row. Weighted neighbor sum (deterministic slot order) +
// fused expmap + proj epilogue.
__global__ void agg_kernel(const float* __restrict__ x,
                           float* __restrict__ out, int N) {
    int row  = blockIdx.x * (blockDim.x >> 5) + (threadIdx.x >> 5);
    int lane = threadIdx.x & 31;
    if (row >= N) return;

    float xi0 = x[row * 64 + lane];
    float xi1 = x[row * 64 + 32 + lane];
    float x2   = g_x2[row];
    float beta = 1.f - x2;
    int c = g_cnt[row];
    int base = row * MAXD;

    float gv0 = (lane < c)      ? g_g[base + lane]      : 0.f;
    float hv0 = (lane < c)      ? g_h[base + lane]      : 0.f;
    int   jv0 = (lane < c)      ? g_j[base + lane]      : 0;
    float gv1 = (lane + 32 < c) ? g_g[base + 32 + lane] : 0.f;
    float hv1 = (lane + 32 < c) ? g_h[base + 32 + lane] : 0.f;
    int   jv1 = (lane + 32 < c) ? g_j[base + 32 + lane] : 0;

    float S1 = warp_sum(hv0 + hv1);     // sum of g*alpha

    float acc0 = 0.f, acc1 = 0.f;
    int c0 = min(c, 32);
#pragma unroll 8
    for (int p = 0; p < c0; p++) {
        float g = __shfl_sync(0xffffffffu, gv0, p);
        int   j = __shfl_sync(0xffffffffu, jv0, p);
        acc0 = fmaf(g, x[j * 64 + lane],      acc0);
        acc1 = fmaf(g, x[j * 64 + 32 + lane], acc1);
    }
    int c1 = c - 32;
#pragma unroll 4
    for (int p = 0; p < c1; p++) {
        float g = __shfl_sync(0xffffffffu, gv1, p);
        int   j = __shfl_sync(0xffffffffu, jv1, p);
        acc0 = fmaf(g, x[j * 64 + lane],      acc0);
        acc1 = fmaf(g, x[j * 64 + 32 + lane], acc1);
    }

    // support_t = beta * (sum g*x_j) - (sum g*alpha) * x_i
    float u0 = fmaf(beta, acc0, -S1 * xi0);
    float u1 = fmaf(beta, acc1, -S1 * xi1);

    // expmap(x_i, u)
    float un2 = warp_sum(u0 * u0 + u1 * u1);
    float du  = warp_sum(xi0 * u0 + xi1 * u1);
    float un  = fmaxf(sqrtf(un2), 1e-15f);
    float lam = fmaxf(2.f / beta, 1e-15f);
    float t   = tanhf(0.5f * lam * un);
    float sc  = t / un;
    float s0 = sc * u0, s1 = sc * u1;
    float y2s = sc * sc * un2;
    float xys = sc * du;
    float ca   = 1.f + 2.f * xys + y2s;
    float den2 = fmaxf(1.f + 2.f * xys + x2 * y2s, 1e-15f);
    float o0 = (ca * xi0 + beta * s0) / den2;
    float o1 = (ca * xi1 + beta * s1) / den2;

    // proj
    float on = fmaxf(sqrtf(warp_sum(o0 * o0 + o1 * o1)), 1e-15f);
    float maxn = 1.f - 0.004f;
    float scale = (on > maxn) ? (maxn / on) : 1.f;
    out[row * 64 + lane]      = o0 * scale;
    out[row * 64 + 32 + lane] = o1 * scale;
}

extern "C" void kernel_launch(void* const* d_in, const int* in_sizes, int n_in,
                              void* d_out, int out_size) {
    const float* x     = (const float*)d_in[0];
    const float* adj   = (const float*)d_in[1];
    const float* att_w = (const float*)d_in[2];
    const float* att_b = (const float*)d_in[3];
    int d = in_sizes[2] / 2;          // 64
    int N = in_sizes[0] / d;          // 1536

    const int WPB = 8;
    dim3 blk(32 * WPB);
    int grid_rows = (N + WPB - 1) / WPB;

    scan_kernel<<<grid_rows, blk>>>(x, adj, att_w, N);
    pair_kernel<<<1536, 256>>>(x, att_b, N);
    agg_kernel<<<grid_rows, blk>>>(x, (float*)d_out, N);
}

// round 5
// speedup vs baseline: 2.4010x; 2.4010x over previous
#include <cuda_runtime.h>
#include <math.h>

__device__ __forceinline__ float warp_sum(float v) {
#pragma unroll
    for (int o = 16; o; o >>= 1) v += __shfl_xor_sync(0xffffffffu, v, o);
    return v;
}

// One block (128 threads / 4 warps) per row i. Fully fused:
//   phase A: row scalars + adj-row scan/compaction (deterministic, no atomics)
//   phase B: lane-parallel per-pair hyperbolic math (y2, r_j computed inline)
//   phase C: dim-parallel weighted gather (split across both thread halves)
//   phase D: expmap + proj epilogue (warp 0)
__global__ __launch_bounds__(128, 12)
void fused_kernel(const float* __restrict__ x,
                  const float* __restrict__ adj,
                  const float* __restrict__ att_w,
                  const float* __restrict__ att_b,
                  float* __restrict__ out, int N) {
    __shared__ float s_xi[64];
    __shared__ float s_wr[64];
    __shared__ float s_x2, s_li, s_S1;
    __shared__ int   s_wcnt[4];
    __shared__ int   s_woff[4];
    __shared__ int   s_tmp[4 * 64];   // per-warp compact lists
    __shared__ int   s_list[128];     // contiguous neighbor list
    __shared__ float s_g[128];        // per-pair weight g
    __shared__ float s_h[128];        // per-pair g*alpha
    __shared__ float s_acc0[64];      // gather partial (even slots)
    __shared__ float s_acc1[64];      // gather partial (odd slots)
    __shared__ float s_u[64];         // tangent vector u
    __shared__ int   s_cnt;

    int row  = blockIdx.x;
    int tid  = threadIdx.x;
    int w    = tid >> 5;
    int lane = tid & 31;

    // stage x_i and w_r
    if (tid < 64) {
        s_xi[tid] = x[row * 64 + tid];
        s_wr[tid] = att_w[64 + tid];
    }
    __syncthreads();

    // warp 0: ||x_i||^2 and l_i
    if (w == 0) {
        float x0 = s_xi[lane], x1 = s_xi[lane + 32];
        float n2 = warp_sum(x0 * x0 + x1 * x1);
        float dl = warp_sum(x0 * att_w[lane] + x1 * att_w[32 + lane]);
        if (lane == 0) {
            s_x2 = n2;
            float pn  = sqrtf(n2);
            float pnc = fmaxf(pn, 1e-15f);
            s_li = atanhf(fminf(pnc, 1.f - 1e-7f)) / pnc * dl;
        }
    }

    // adj-row scan: warp w covers float4s [w*qpw, (w+1)*qpw)
    const float4* arow = (const float4*)(adj + (size_t)row * N);
    int nq  = N >> 2;
    int qpw = (nq + 3) >> 2;
    int qb  = w * qpw;
    float4 v[3];
#pragma unroll
    for (int c = 0; c < 3; c++) {
        int qi = qb + c * 32 + lane;
        v[c] = (c * 32 + lane < qpw && qi < nq) ? __ldg(&arow[qi])
                                                : make_float4(0.f, 0.f, 0.f, 0.f);
    }
    int cw = 0;
#pragma unroll
    for (int c = 0; c < 3; c++) {
        float vals[4] = {v[c].x, v[c].y, v[c].z, v[c].w};
#pragma unroll
        for (int e = 0; e < 4; e++) {
            unsigned m = __ballot_sync(0xffffffffu, vals[e] != 0.f);
            if (vals[e] != 0.f) {
                int slot = cw + __popc(m & ((1u << lane) - 1u));
                if (slot < 64) s_tmp[w * 64 + slot] = (qb + c * 32 + lane) * 4 + e;
            }
            cw += __popc(m);
        }
    }
    if (lane == 0) s_wcnt[w] = min(cw, 64);
    __syncthreads();

    if (tid == 0) {
        int o = 0;
#pragma unroll
        for (int i = 0; i < 4; i++) { s_woff[i] = o; o += s_wcnt[i]; }
        s_cnt = min(o, 128);
    }
    __syncthreads();
    {
        int o = s_woff[w], n = s_wcnt[w];
        for (int s = lane; s < n; s += 32)
            if (o + s < 128) s_list[o + s] = s_tmp[w * 64 + s];
    }
    __syncthreads();

    int   cnt  = s_cnt;
    float x2   = s_x2;
    float li   = s_li;
    float beta = 1.f - x2;
    float bias = att_b[0];

    // phase B: lane-parallel pair math. Thread t owns neighbor t.
    if (tid < cnt) {
        int j = s_list[tid];
        const float4* xj = (const float4*)(x + j * 64);
        float D = 0.f, y2 = 0.f, rd = 0.f;
#pragma unroll
        for (int k = 0; k < 16; k++) {
            float4 q = __ldg(&xj[k]);
            D  = fmaf(q.x, s_xi[4*k],   fmaf(q.y, s_xi[4*k+1],
                 fmaf(q.z, s_xi[4*k+2], fmaf(q.w, s_xi[4*k+3], D))));
            y2 = fmaf(q.x, q.x, fmaf(q.y, q.y, fmaf(q.z, q.z, fmaf(q.w, q.w, y2))));
            rd = fmaf(q.x, s_wr[4*k],   fmaf(q.y, s_wr[4*k+1],
                 fmaf(q.z, s_wr[4*k+2], fmaf(q.w, s_wr[4*k+3], rd))));
        }
        float pnj  = sqrtf(y2);
        float pnjc = fmaxf(pnj, 1e-15f);
        float rv   = atanhf(fminf(pnjc, 1.f - 1e-7f)) / pnjc * rd;  // r_j
        float alpha = 1.f - 2.f * D + y2;
        float den   = fmaxf(1.f - 2.f * D + x2 * y2, 1e-15f);
        float n2    = alpha * alpha * x2 - 2.f * alpha * beta * D
                    + beta * beta * y2;
        float sn    = fmaxf(sqrtf(fmaxf(n2, 0.f)) / den, 1e-15f);
        float ratio = atanhf(fminf(sn, 1.f - 1e-7f)) / sn;
        float sig   = 1.f / (1.f + expf(-(li + rv + bias)));   // adj val == 1
        float g     = sig * beta * ratio / den;
        s_g[tid] = g;
        s_h[tid] = g * alpha;
    }
    __syncthreads();

    // S1 = sum g*alpha (warp 0, deterministic)
    if (w == 0) {
        float hv = (lane < cnt ? s_h[lane] : 0.f)
                 + (lane + 32 < cnt ? s_h[lane + 32] : 0.f);
        float S1 = warp_sum(hv);
        if (lane == 0) s_S1 = S1;
    }
    __syncthreads();

    // phase C: dim-parallel gather split by slot parity across thread halves.
    // half 0 (tid<64): even slots;  half 1 (tid>=64): odd slots.
    {
        int dd   = tid & 63;
        int par  = tid >> 6;            // 0 or 1
        float acc = 0.f;
        for (int s = par; s < cnt; s += 2)
            acc = fmaf(s_g[s], __ldg(&x[s_list[s] * 64 + dd]), acc);
        if (par == 0) s_acc0[dd] = acc; else s_acc1[dd] = acc;
    }
    __syncthreads();
    if (tid < 64) {
        float acc = s_acc0[tid] + s_acc1[tid];
        s_u[tid] = fmaf(beta, acc, -s_S1 * s_xi[tid]);
    }
    __syncthreads();

    // phase D: expmap + proj epilogue (warp 0, 2 dims/lane)
    if (w == 0) {
        float xi0 = s_xi[lane], xi1 = s_xi[lane + 32];
        float u0  = s_u[lane],  u1  = s_u[lane + 32];
        float un2 = warp_sum(u0 * u0 + u1 * u1);
        float du  = warp_sum(xi0 * u0 + xi1 * u1);
        float un  = fmaxf(sqrtf(un2), 1e-15f);
        float lam = fmaxf(2.f / beta, 1e-15f);
        float t   = tanhf(0.5f * lam * un);
        float sc  = t / un;
        float s0 = sc * u0, s1 = sc * u1;
        float y2s = sc * sc * un2;
        float xys = sc * du;
        float ca   = 1.f + 2.f * xys + y2s;
        float den2 = fmaxf(1.f + 2.f * xys + x2 * y2s, 1e-15f);
        float o0 = (ca * xi0 + beta * s0) / den2;
        float o1 = (ca * xi1 + beta * s1) / den2;
        float on = fmaxf(sqrtf(warp_sum(o0 * o0 + o1 * o1)), 1e-15f);
        float maxn  = 1.f - 0.004f;
        float scale = (on > maxn) ? (maxn / on) : 1.f;
        out[row * 64 + lane]      = o0 * scale;
        out[row * 64 + 32 + lane] = o1 * scale;
    }
}

extern "C" void kernel_launch(void* const* d_in, const int* in_sizes, int n_in,
                              void* d_out, int out_size) {
    const float* x     = (const float*)d_in[0];
    const float* adj   = (const float*)d_in[1];
    const float* att_w = (const float*)d_in[2];
    const float* att_b = (const float*)d_in[3];
    int d = in_sizes[2] / 2;          // 64
    int N = in_sizes[0] / d;          // 1536
    fused_kernel<<<N, 128>>>(x, adj, att_w, att_b, (float*)d_out, N);
}